// round 2
// baseline (speedup 1.0000x reference)
#include <cuda_runtime.h>
#include <math.h>

// GeoFeaturizer for GB300 (sm_103a). B=8 batches, K=3 virtual frames (fixed).
#define NB 8
#define KF 3
#define NMAX 30016     // >= N (30000)
#define TILE 128       // edges per block in the edge kernel
#define EW 213         // edge feature width (152 diffE + 9 quant + 19 trans + 16 pos + 17 bias)

struct __align__(16) Frame { float4 r0, r1, r2; };  // rows of stored R; .w = t component
__device__ Frame g_frames[NMAX];

// pos-embedding freqs: 10000^(-j/8) = 10^(-j/2)
__constant__ float c_posfreq[8] = {
    1.0f, 0.31622776601683794f, 0.1f, 0.031622776601683794f,
    0.01f, 0.0031622776601683794f, 0.001f, 0.00031622776601683794f
};

__device__ __forceinline__ void stg(float* __restrict__ o, long long i, float v, long long lim) {
    if (i >= 0 && i < lim) o[i] = v;
}

// decouple() for a 3-vector: 3 direction comps + 16 RBF of the norm
__device__ __forceinline__ void dec3(float* __restrict__ w, float x, float y, float z) {
    float sq   = x*x + y*y + z*z;
    float norm = sqrtf(sq + 1e-12f);
    float inv  = (norm < 1e-4f) ? 0.f : 1.f / (norm + 1e-6f);
    w[0] = x * inv; w[1] = y * inv; w[2] = z * inv;
#pragma unroll
    for (int r = 0; r < 16; r++) {
        float u = (norm - (float)r * (20.0f / 15.0f)) * 0.8f;   // sigma = 1.25
        w[3 + r] = expf(-u * u);
    }
}

// ---------------------------------------------------------------------------
// Kernel 1: per-node frames + node features V + T_rot/T_trans/batch/chain
// ---------------------------------------------------------------------------
__global__ void node_kernel(const float* __restrict__ X,
                            const int*  __restrict__ batch_id,
                            const int*  __restrict__ chain,
                            float* __restrict__ out, long long LIM,
                            int N,
                            long long OFF_V, long long OFF_TROT, long long OFF_TTRANS,
                            long long OFF_BATCH, long long OFF_CHAIN) {
    int n = blockIdx.x * blockDim.x + threadIdx.x;
    if (n >= N) return;

    const float* xr = X + (size_t)n * 12;
    float ax[4][3];
#pragma unroll
    for (int a = 0; a < 4; a++)
#pragma unroll
        for (int j = 0; j < 3; j++) ax[a][j] = xr[a * 3 + j];

    float ca0 = ax[1][0], ca1 = ax[1][1], ca2 = ax[1][2];
    float nx = ax[0][0] - ca0, ny_ = ax[0][1] - ca1, nz_ = ax[0][2] - ca2;
    float cx = ax[2][0] - ca0, cy  = ax[2][1] - ca1, cz  = ax[2][2] - ca2;

    const float EPSf = 1e-20f;
    float nrm  = sqrtf(EPSf + cx*cx + cy*cy);
    float s1 = -cy / nrm, c1 = cx / nrm;
    float nrm2 = sqrtf(EPSf + cx*cx + cy*cy + cz*cz);
    float s2 = cz / nrm2;
    float c2 = sqrtf(cx*cx + cy*cy) / nrm2;

    // Rc = R2 @ R1 (rows)
    float Rc[3][3] = {
        { c2*c1, -c2*s1, s2 },
        { s1,     c1,    0.f},
        {-s2*c1,  s2*s1, c2 }
    };
    // nrot = Rc @ n  (only comps 1,2 needed)
    float nr1 = Rc[1][0]*nx + Rc[1][1]*ny_;
    float nr2 = Rc[2][0]*nx + Rc[2][1]*ny_ + Rc[2][2]*nz_;
    float nrm3 = sqrtf(EPSf + nr1*nr1 + nr2*nr2);
    float sn = -nr2 / nrm3, cn = nr1 / nrm3;

    float M[3][3];
#pragma unroll
    for (int j = 0; j < 3; j++) {
        M[0][j] = Rc[0][j];
        M[1][j] = cn * Rc[1][j] - sn * Rc[2][j];
        M[2][j] = sn * Rc[1][j] + cn * Rc[2][j];
    }
    float R[3][3];  // stored R = M^T (this equals the reference's R)
#pragma unroll
    for (int i = 0; i < 3; i++)
#pragma unroll
        for (int j = 0; j < 3; j++) R[i][j] = M[j][i];

    Frame f;
    f.r0 = make_float4(R[0][0], R[0][1], R[0][2], ca0);
    f.r1 = make_float4(R[1][0], R[1][1], R[1][2], ca1);
    f.r2 = make_float4(R[2][0], R[2][1], R[2][2], ca2);
    g_frames[n] = f;

#pragma unroll
    for (int i = 0; i < 3; i++)
#pragma unroll
        for (int j = 0; j < 3; j++)
            stg(out, OFF_TROT + (long long)n * 9 + 3 * i + j, R[i][j], LIM);
    stg(out, OFF_TTRANS + (long long)n * 3 + 0, ca0, LIM);
    stg(out, OFF_TTRANS + (long long)n * 3 + 1, ca1, LIM);
    stg(out, OFF_TTRANS + (long long)n * 3 + 2, ca2, LIM);

    stg(out, OFF_BATCH + n, (float)batch_id[n], LIM);
    stg(out, OFF_CHAIN + n, (float)chain[n], LIM);

    // node features V
    bool start = (n == 0) || (batch_id[n] != batch_id[n - 1]);
    float prev0 = 0.f, prev1 = 0.f, prev2 = 0.f;
    if (n > 0) {
        const float* xp = X + (size_t)(n - 1) * 12 + 9;  // previous node, atom 3
        prev0 = xp[0]; prev1 = xp[1]; prev2 = xp[2];
    }
    float vbuf[19];
#pragma unroll
    for (int a = 0; a < 4; a++) {
        float dx, dy, dz;
        if (start) { dx = dy = dz = 0.f; }
        else {
            float px, py, pz;
            if (a == 0) { px = prev0; py = prev1; pz = prev2; }
            else        { px = ax[a-1][0]; py = ax[a-1][1]; pz = ax[a-1][2]; }
            dx = ax[a][0] - px; dy = ax[a][1] - py; dz = ax[a][2] - pz;
        }
        // dX_loc = R^T d: out_i = sum_j R[j][i] d_j
        float l0 = R[0][0]*dx + R[1][0]*dy + R[2][0]*dz;
        float l1 = R[0][1]*dx + R[1][1]*dy + R[2][1]*dz;
        float l2 = R[0][2]*dx + R[1][2]*dy + R[2][2]*dz;
        dec3(vbuf, l0, l1, l2);
#pragma unroll
        for (int c = 0; c < 19; c++)
            stg(out, OFF_V + (long long)n * 76 + a * 19 + c, vbuf[c], LIM);
    }
}

// ---------------------------------------------------------------------------
// Kernel 2: per-edge features, staged in shared memory (pitch == EW, layout
// identical to global), then one contiguous coalesced float4 copy out.
// ---------------------------------------------------------------------------
__global__ void edge_kernel(const float* __restrict__ X,
                            const int*  __restrict__ eix,       // (2, E) row-major
                            const int*  __restrict__ node_idx,
                            float* __restrict__ out, long long LIM,
                            int N, int E, int ET,
                            long long OFF_E, long long OFF_TTSROT,
                            long long OFF_TTSTRANS, long long OFF_EIDX) {
    extern __shared__ float sm[];
    int tid = threadIdx.x;
    int e0  = blockIdx.x * TILE;
    int e   = e0 + tid;

    if (e < E) {
        float* w = sm + tid * EW;
        int s = min(max(eix[e], 0), N - 1);
        int d = min(max(eix[E + e], 0), N - 1);

        Frame Fs = g_frames[s], Fd = g_frames[d];
        float Rs[3][3] = {{Fs.r0.x, Fs.r0.y, Fs.r0.z},
                          {Fs.r1.x, Fs.r1.y, Fs.r1.z},
                          {Fs.r2.x, Fs.r2.y, Fs.r2.z}};
        float Rd[3][3] = {{Fd.r0.x, Fd.r0.y, Fd.r0.z},
                          {Fd.r1.x, Fd.r1.y, Fd.r1.z},
                          {Fd.r2.x, Fd.r2.y, Fd.r2.z}};
        float ts[3] = {Fs.r0.w, Fs.r1.w, Fs.r2.w};
        float td[3] = {Fd.r0.w, Fd.r1.w, Fd.r2.w};

        const float4* Xs4 = reinterpret_cast<const float4*>(X) + (size_t)s * 3;
        const float4* Xd4 = reinterpret_cast<const float4*>(X) + (size_t)d * 3;
        float4 sa = Xs4[0], sb = Xs4[1], sc = Xs4[2];
        float4 da = Xd4[0], db = Xd4[1], dc = Xd4[2];
        float P[8][3] = {
            {sa.x, sa.y, sa.z}, {sa.w, sb.x, sb.y}, {sb.z, sb.w, sc.x}, {sc.y, sc.z, sc.w},
            {da.x, da.y, da.z}, {da.w, db.x, db.y}, {db.z, db.w, dc.x}, {dc.y, dc.z, dc.w}
        };

        // diffE: loc = Rs^T (p - t_src), decoupled (cols 0..151)
#pragma unroll
        for (int a8 = 0; a8 < 8; a8++) {
            float q0 = P[a8][0] - ts[0], q1 = P[a8][1] - ts[1], q2 = P[a8][2] - ts[2];
            float l0 = Rs[0][0]*q0 + Rs[1][0]*q1 + Rs[2][0]*q2;
            float l1 = Rs[0][1]*q0 + Rs[1][1]*q1 + Rs[2][1]*q2;
            float l2 = Rs[0][2]*q0 + Rs[1][2]*q1 + Rs[2][2]*q2;
            dec3(w + a8 * 19, l0, l1, l2);
        }

        // Q[i][j] = (Rs^T Rd)[i][j];  Rts = Q^T;  E_quant = Rts^T = Q (cols 152..160)
        float Q[3][3];
#pragma unroll
        for (int i = 0; i < 3; i++)
#pragma unroll
            for (int j = 0; j < 3; j++)
                Q[i][j] = Rs[0][i]*Rd[0][j] + Rs[1][i]*Rd[1][j] + Rs[2][i]*Rd[2][j];
#pragma unroll
        for (int i = 0; i < 3; i++)
#pragma unroll
            for (int j = 0; j < 3; j++)
                w[152 + 3 * i + j] = Q[i][j];

        // Tts_rot = Rts row-major: Rts[i][k] = Q[k][i]
#pragma unroll
        for (int i = 0; i < 3; i++)
#pragma unroll
            for (int k = 0; k < 3; k++)
                stg(out, OFF_TTSROT + (long long)e * 9 + 3 * i + k, Q[k][i], LIM);

        // tts = Rd^T (t_src - t_dst); E_trans (cols 161..179)
        float dt0 = ts[0] - td[0], dt1 = ts[1] - td[1], dt2 = ts[2] - td[2];
        float t0 = Rd[0][0]*dt0 + Rd[1][0]*dt1 + Rd[2][0]*dt2;
        float t1 = Rd[0][1]*dt0 + Rd[1][1]*dt1 + Rd[2][1]*dt2;
        float t2 = Rd[0][2]*dt0 + Rd[1][2]*dt1 + Rd[2][2]*dt2;
        dec3(w + 161, t0, t1, t2);
        stg(out, OFF_TTSTRANS + (long long)e * 3 + 0, t0, LIM);
        stg(out, OFF_TTSTRANS + (long long)e * 3 + 1, t1, LIM);
        stg(out, OFF_TTSTRANS + (long long)e * 3 + 2, t2, LIM);

        // pos embedding (cols 180..195): double sin/cos for robust range reduction
        float dd = (float)(s - d);
#pragma unroll
        for (int j = 0; j < 8; j++) {
            float ang = __fmul_rn(dd, c_posfreq[j]);
            double si, co;
            sincos((double)ang, &si, &co);
            w[180 + j] = (float)co;
            w[188 + j] = (float)si;
        }

        // E_bias (cols 196..212): decouple of a 1-vector -> 1 direct + 16 RBF
        float bb = (float)(node_idx[s] - node_idx[d]);
        float nb = sqrtf(bb * bb + 1e-12f);
        float ib = (nb < 1e-4f) ? 0.f : 1.f / (nb + 1e-6f);
        w[196] = bb * ib;
#pragma unroll
        for (int r = 0; r < 16; r++) {
            float u = (nb - (float)r * (20.0f / 15.0f)) * 0.8f;
            w[197 + r] = expf(-u * u);
        }

        // edge index outputs
        stg(out, OFF_EIDX + e,      (float)eix[e],     LIM);
        stg(out, OFF_EIDX + ET + e, (float)eix[E + e], LIM);
    }
    __syncthreads();

    // contiguous coalesced float4 copy out (smem layout == global layout)
    int rem   = min(TILE, E - e0);
    int total = rem * EW;
    long long base = OFF_E + (long long)e0 * EW;   // base % 4 == 0 (128*213 and OFF_E are mult of 4)
    float4* g4 = reinterpret_cast<float4*>(out + base);
    const float4* s4 = reinterpret_cast<const float4*>(sm);
    int n4 = total >> 2;
    long long lim4 = (LIM - base) >> 2;
    for (int k4 = tid; k4 < n4; k4 += TILE)
        if (k4 < lim4) g4[k4] = s4[k4];
    for (int k = (n4 << 2) + tid; k < total; k += TILE)
        stg(out, base + k, sm[k], LIM);
}

// ---------------------------------------------------------------------------
// Kernel 3: big zero fill for E_g (float4 contiguous)
// ---------------------------------------------------------------------------
__global__ void fill_zero4(float4* __restrict__ p, long long n4) {
    long long stride = (long long)gridDim.x * blockDim.x;
    for (long long i = blockIdx.x * (long long)blockDim.x + threadIdx.x; i < n4; i += stride)
        p[i] = make_float4(0.f, 0.f, 0.f, 0.f);
}

// ---------------------------------------------------------------------------
// Kernel 4: virtual-frame tails (identities, index tails, V_g, batch/chain)
// ---------------------------------------------------------------------------
__global__ void misc_kernel(const int* __restrict__ batch_id, float* __restrict__ out,
                            long long LIM, int N, int E,
                            long long OFF_V, long long OFF_TROT, long long OFF_TTRANS,
                            long long OFF_TTSROT, long long OFF_TTSTRANS,
                            long long OFF_BATCH, long long OFF_EIDX, long long OFF_CHAIN) {
    const int KN = KF * N, G2 = 2 * KN, ET = E + G2, KB = KF * NB;
    const long long szA = (long long)G2 * 9;   // Tts_rot tail (identity)
    const long long szB = (long long)G2 * 3;   // Tts_trans tail (zeros)
    const long long szC = 2LL * G2;            // eidx tails
    const long long szD = KB;                  // batch tail
    const long long szE_ = KB;                 // chain tail
    const long long szF = (long long)KB * 9;   // T_rot tail (identity)
    const long long szG = (long long)KB * 3;   // T_trans tail (zeros)
    const long long szH = (long long)KB * 76;  // V_g
    const long long TOT = szA + szB + szC + szD + szE_ + szF + szG + szH;

    long long stride = (long long)gridDim.x * blockDim.x;
    for (long long i = blockIdx.x * (long long)blockDim.x + threadIdx.x; i < TOT; i += stride) {
        long long j = i;
        if (j < szA) {
            int c = (int)(j % 9);
            stg(out, OFF_TTSROT + (long long)E * 9 + j, (c == 0 || c == 4 || c == 8) ? 1.f : 0.f, LIM);
            continue;
        }
        j -= szA;
        if (j < szB) { stg(out, OFF_TTSTRANS + (long long)E * 3 + j, 0.f, LIM); continue; }
        j -= szB;
        if (j < szC) {
            int jj = (int)j;
            if (jj < G2) {  // row 0: [g_src(KN), g_dst(KN)]
                float v = (jj < KN)
                          ? (float)(N + batch_id[jj % N] + (jj / N) * NB)
                          : (float)((jj - KN) % N);
                stg(out, OFF_EIDX + E + jj, v, LIM);
            } else {        // row 1: [g_dst(KN), g_src(KN)]
                int t = jj - G2;
                float v = (t < KN)
                          ? (float)(t % N)
                          : (float)(N + batch_id[(t - KN) % N] + ((t - KN) / N) * NB);
                stg(out, OFF_EIDX + ET + E + t, v, LIM);
            }
            continue;
        }
        j -= szC;
        if (j < szD) { stg(out, OFF_BATCH + N + j, (float)((int)j % NB), LIM); continue; }
        j -= szD;
        if (j < szE_) { stg(out, OFF_CHAIN + N + j, 1001.f, LIM); continue; }
        j -= szE_;
        if (j < szF) {
            int c = (int)(j % 9);
            stg(out, OFF_TROT + (long long)N * 9 + j, (c == 0 || c == 4 || c == 8) ? 1.f : 0.f, LIM);
            continue;
        }
        j -= szF;
        if (j < szG) { stg(out, OFF_TTRANS + (long long)N * 3 + j, 0.f, LIM); continue; }
        j -= szG;
        {
            int r = (int)(j / 76), c = (int)(j % 76);
            int k = r / NB;
            int m = (c < 38) ? c : c - 38;
            double f = exp(-(double)(2 * m) * 9.210340371976184 / 76.0);
            double ang = (double)k * f;
            stg(out, OFF_V + (long long)(N + r) * 76 + c, (float)((c < 38) ? cos(ang) : sin(ang)), LIM);
        }
    }
}

// ---------------------------------------------------------------------------
extern "C" void kernel_launch(void* const* d_in, const int* in_sizes, int n_in,
                              void* d_out, int out_size) {
    const float* X        = (const float*)d_in[0];
    const int*   node_idx = (const int*)d_in[1];
    const int*   eix      = (const int*)d_in[2];
    const int*   batch_id = (const int*)d_in[3];
    const int*   chain    = (const int*)d_in[4];
    float* out = (float*)d_out;

    int N = in_sizes[0] / 12;
    int E = in_sizes[2] / 2;
    int NT = N + KF * NB;
    int G2 = 2 * KF * N;
    int ET = E + G2;
    long long LIM = (long long)out_size;

    long long OFF_V        = 0;
    long long OFF_E        = OFF_V + (long long)NT * 76;
    long long OFF_TROT     = OFF_E + (long long)ET * EW;
    long long OFF_TTRANS   = OFF_TROT + (long long)NT * 9;
    long long OFF_TTSROT   = OFF_TTRANS + (long long)NT * 3;
    long long OFF_TTSTRANS = OFF_TTSROT + (long long)ET * 9;
    long long OFF_BATCH    = OFF_TTSTRANS + (long long)ET * 3;
    long long OFF_EIDX     = OFF_BATCH + NT;
    long long OFF_CHAIN    = OFF_EIDX + 2LL * ET;

    static bool attr_done = false;
    if (!attr_done) {
        cudaFuncSetAttribute(edge_kernel, cudaFuncAttributeMaxDynamicSharedMemorySize,
                             TILE * EW * (int)sizeof(float));
        attr_done = true;
    }

    node_kernel<<<(N + 127) / 128, 128>>>(X, batch_id, chain, out, LIM, N,
                                          OFF_V, OFF_TROT, OFF_TTRANS, OFF_BATCH, OFF_CHAIN);

    edge_kernel<<<(E + TILE - 1) / TILE, TILE, TILE * EW * sizeof(float)>>>(
        X, eix, node_idx, out, LIM, N, E, ET, OFF_E, OFF_TTSROT, OFF_TTSTRANS, OFF_EIDX);

    // E_g zero region: rows [E, ET) of E_out, contiguous & 16B-aligned
    long long zstart = OFF_E + (long long)E * EW;
    long long zcount = (long long)G2 * EW;
    long long n4 = zcount / 4;
    if (zstart + zcount <= LIM)
        fill_zero4<<<2048, 256>>>(reinterpret_cast<float4*>(out + zstart), n4);

    misc_kernel<<<4096, 256>>>(batch_id, out, LIM, N, E,
                               OFF_V, OFF_TROT, OFF_TTRANS, OFF_TTSROT, OFF_TTSTRANS,
                               OFF_BATCH, OFF_EIDX, OFF_CHAIN);
}

// round 3
// speedup vs baseline: 2.3251x; 2.3251x over previous
#include <cuda_runtime.h>
#include <math.h>

// GeoFeaturizer for GB300 (sm_103a). B=8 batches, K=3 virtual frames (fixed).
#define NB 8
#define KF 3
#define NMAX 30016     // >= N (30000)
#define TILE 128       // edges per block in the edge kernel
#define EW 213         // edge feature width (152 diffE + 9 quant + 19 trans + 16 pos + 17 bias)

struct __align__(16) Frame { float4 r0, r1, r2; };  // rows of stored R; .w = t component
__device__ Frame g_frames[NMAX];

// pos-embedding freqs: 10000^(-j/8) = 10^(-j/2)
__constant__ float c_posfreq[8] = {
    1.0f, 0.31622776601683794f, 0.1f, 0.031622776601683794f,
    0.01f, 0.0031622776601683794f, 0.001f, 0.00031622776601683794f
};

__device__ __forceinline__ void stg(float* __restrict__ o, long long i, float v, long long lim) {
    if (i >= 0 && i < lim) o[i] = v;
}

// decouple() for a 3-vector: 3 direction comps + 16 RBF of the norm. All f32 fast-path.
__device__ __forceinline__ void dec3(float* __restrict__ w, float x, float y, float z) {
    float sq   = x*x + y*y + z*z;
    float norm = sqrtf(sq + 1e-12f);
    float inv  = (norm < 1e-4f) ? 0.f : __fdividef(1.f, norm + 1e-6f);
    w[0] = x * inv; w[1] = y * inv; w[2] = z * inv;
    float a = 0.8f * norm;
#pragma unroll
    for (int r = 0; r < 16; r++) {
        float u = a - (float)r * 1.0666666666666667f;
        w[3 + r] = __expf(-u * u);
    }
}

// f32 Cody-Waite reduction of ang (|ang| <= ~3.2e4) then fast sin/cos.
__device__ __forceinline__ void fast_sincos(float ang, float* s, float* c) {
    const float INV2PI = 0.15915494309189535f;
    const float PI2_HI = 6.28318548202514648f;    // f32(2*pi)
    const float PI2_LO = -1.74845553146357e-07f;  // 2*pi - PI2_HI
    float k = rintf(ang * INV2PI);
    float r = fmaf(-k, PI2_HI, ang);
    r = fmaf(-k, PI2_LO, r);
    *s = __sinf(r);
    *c = __cosf(r);
}

// ---------------------------------------------------------------------------
// Kernel 1: per-node frames + node features V + T_rot/T_trans/batch/chain
// ---------------------------------------------------------------------------
__global__ void node_kernel(const float* __restrict__ X,
                            const int*  __restrict__ batch_id,
                            const int*  __restrict__ chain,
                            float* __restrict__ out, long long LIM,
                            int N,
                            long long OFF_V, long long OFF_TROT, long long OFF_TTRANS,
                            long long OFF_BATCH, long long OFF_CHAIN) {
    __shared__ float sv[128 * 76];
    int tid = threadIdx.x;
    int n0  = blockIdx.x * 128;
    int n   = n0 + tid;

    if (n < N) {
        const float4* X4 = reinterpret_cast<const float4*>(X) + (size_t)n * 3;
        float4 xa = X4[0], xb = X4[1], xc = X4[2];
        float ax[4][3] = {
            {xa.x, xa.y, xa.z}, {xa.w, xb.x, xb.y},
            {xb.z, xb.w, xc.x}, {xc.y, xc.z, xc.w}
        };

        float ca0 = ax[1][0], ca1 = ax[1][1], ca2 = ax[1][2];
        float nx = ax[0][0] - ca0, ny_ = ax[0][1] - ca1, nz_ = ax[0][2] - ca2;
        float cx = ax[2][0] - ca0, cy  = ax[2][1] - ca1, cz  = ax[2][2] - ca2;

        const float EPSf = 1e-20f;
        float nrm  = sqrtf(EPSf + cx*cx + cy*cy);
        float s1 = -cy / nrm, c1 = cx / nrm;
        float nrm2 = sqrtf(EPSf + cx*cx + cy*cy + cz*cz);
        float s2 = cz / nrm2;
        float c2 = sqrtf(cx*cx + cy*cy) / nrm2;

        float Rc[3][3] = {
            { c2*c1, -c2*s1, s2 },
            { s1,     c1,    0.f},
            {-s2*c1,  s2*s1, c2 }
        };
        float nr1 = Rc[1][0]*nx + Rc[1][1]*ny_;
        float nr2 = Rc[2][0]*nx + Rc[2][1]*ny_ + Rc[2][2]*nz_;
        float nrm3 = sqrtf(EPSf + nr1*nr1 + nr2*nr2);
        float sn = -nr2 / nrm3, cn = nr1 / nrm3;

        float M[3][3];
#pragma unroll
        for (int j = 0; j < 3; j++) {
            M[0][j] = Rc[0][j];
            M[1][j] = cn * Rc[1][j] - sn * Rc[2][j];
            M[2][j] = sn * Rc[1][j] + cn * Rc[2][j];
        }
        float R[3][3];  // stored R = M^T
#pragma unroll
        for (int i = 0; i < 3; i++)
#pragma unroll
            for (int j = 0; j < 3; j++) R[i][j] = M[j][i];

        Frame f;
        f.r0 = make_float4(R[0][0], R[0][1], R[0][2], ca0);
        f.r1 = make_float4(R[1][0], R[1][1], R[1][2], ca1);
        f.r2 = make_float4(R[2][0], R[2][1], R[2][2], ca2);
        g_frames[n] = f;

#pragma unroll
        for (int i = 0; i < 3; i++)
#pragma unroll
            for (int j = 0; j < 3; j++)
                stg(out, OFF_TROT + (long long)n * 9 + 3 * i + j, R[i][j], LIM);
        stg(out, OFF_TTRANS + (long long)n * 3 + 0, ca0, LIM);
        stg(out, OFF_TTRANS + (long long)n * 3 + 1, ca1, LIM);
        stg(out, OFF_TTRANS + (long long)n * 3 + 2, ca2, LIM);
        stg(out, OFF_BATCH + n, (float)batch_id[n], LIM);
        stg(out, OFF_CHAIN + n, (float)chain[n], LIM);

        // node features V -> smem staging
        bool start = (n == 0) || (batch_id[n] != batch_id[n - 1]);
        float prev0 = 0.f, prev1 = 0.f, prev2 = 0.f;
        if (n > 0) {
            const float* xp = X + (size_t)(n - 1) * 12 + 9;
            prev0 = xp[0]; prev1 = xp[1]; prev2 = xp[2];
        }
        float* wv = sv + tid * 76;
#pragma unroll
        for (int a = 0; a < 4; a++) {
            float dx, dy, dz;
            if (start) { dx = dy = dz = 0.f; }
            else {
                float px, py, pz;
                if (a == 0) { px = prev0; py = prev1; pz = prev2; }
                else        { px = ax[a-1][0]; py = ax[a-1][1]; pz = ax[a-1][2]; }
                dx = ax[a][0] - px; dy = ax[a][1] - py; dz = ax[a][2] - pz;
            }
            float l0 = R[0][0]*dx + R[1][0]*dy + R[2][0]*dz;
            float l1 = R[0][1]*dx + R[1][1]*dy + R[2][1]*dz;
            float l2 = R[0][2]*dx + R[1][2]*dy + R[2][2]*dz;
            dec3(wv + a * 19, l0, l1, l2);
        }
    }
    __syncthreads();

    int rem = min(128, N - n0);
    if (rem > 0) {
        int total = rem * 76;
        long long base = OFF_V + (long long)n0 * 76;   // mult of 4
        float4* g4 = reinterpret_cast<float4*>(out + base);
        const float4* s4 = reinterpret_cast<const float4*>(sv);
        int n4 = total >> 2;
        long long lim4 = (LIM - base) >> 2;
        for (int k4 = tid; k4 < n4; k4 += 128)
            if (k4 < lim4) g4[k4] = s4[k4];
    }
}

// ---------------------------------------------------------------------------
// Kernel 2: per-edge features, smem-staged (layout == global), coalesced out.
// ---------------------------------------------------------------------------
__global__ void edge_kernel(const float* __restrict__ X,
                            const int*  __restrict__ eix,       // (2, E) row-major
                            const int*  __restrict__ node_idx,
                            float* __restrict__ out, long long LIM,
                            int N, int E, int ET,
                            long long OFF_E, long long OFF_TTSROT,
                            long long OFF_TTSTRANS, long long OFF_EIDX) {
    extern __shared__ float sm[];
    int tid = threadIdx.x;
    int e0  = blockIdx.x * TILE;
    int e   = e0 + tid;
    bool active = (e < E);

    float Q[3][3];
    float t0 = 0.f, t1 = 0.f, t2 = 0.f;

    if (active) {
        float* w = sm + tid * EW;
        int s = min(max(eix[e], 0), N - 1);
        int d = min(max(eix[E + e], 0), N - 1);

        Frame Fs = g_frames[s], Fd = g_frames[d];
        float Rs[3][3] = {{Fs.r0.x, Fs.r0.y, Fs.r0.z},
                          {Fs.r1.x, Fs.r1.y, Fs.r1.z},
                          {Fs.r2.x, Fs.r2.y, Fs.r2.z}};
        float Rd[3][3] = {{Fd.r0.x, Fd.r0.y, Fd.r0.z},
                          {Fd.r1.x, Fd.r1.y, Fd.r1.z},
                          {Fd.r2.x, Fd.r2.y, Fd.r2.z}};
        float ts[3] = {Fs.r0.w, Fs.r1.w, Fs.r2.w};
        float td[3] = {Fd.r0.w, Fd.r1.w, Fd.r2.w};

        const float4* Xs4 = reinterpret_cast<const float4*>(X) + (size_t)s * 3;
        const float4* Xd4 = reinterpret_cast<const float4*>(X) + (size_t)d * 3;
        float4 sa = Xs4[0], sb = Xs4[1], sc = Xs4[2];
        float4 da = Xd4[0], db = Xd4[1], dc = Xd4[2];
        float P[8][3] = {
            {sa.x, sa.y, sa.z}, {sa.w, sb.x, sb.y}, {sb.z, sb.w, sc.x}, {sc.y, sc.z, sc.w},
            {da.x, da.y, da.z}, {da.w, db.x, db.y}, {db.z, db.w, dc.x}, {dc.y, dc.z, dc.w}
        };

        // diffE: loc = Rs^T (p - t_src), decoupled (cols 0..151)
#pragma unroll
        for (int a8 = 0; a8 < 8; a8++) {
            float q0 = P[a8][0] - ts[0], q1 = P[a8][1] - ts[1], q2 = P[a8][2] - ts[2];
            float l0 = Rs[0][0]*q0 + Rs[1][0]*q1 + Rs[2][0]*q2;
            float l1 = Rs[0][1]*q0 + Rs[1][1]*q1 + Rs[2][1]*q2;
            float l2 = Rs[0][2]*q0 + Rs[1][2]*q1 + Rs[2][2]*q2;
            dec3(w + a8 * 19, l0, l1, l2);
        }

        // Q = Rs^T Rd; E_quant (cols 152..160) = Q row-major
#pragma unroll
        for (int i = 0; i < 3; i++)
#pragma unroll
            for (int j = 0; j < 3; j++)
                Q[i][j] = Rs[0][i]*Rd[0][j] + Rs[1][i]*Rd[1][j] + Rs[2][i]*Rd[2][j];
#pragma unroll
        for (int i = 0; i < 3; i++)
#pragma unroll
            for (int j = 0; j < 3; j++)
                w[152 + 3 * i + j] = Q[i][j];

        // tts = Rd^T (t_src - t_dst); E_trans (cols 161..179)
        float dt0 = ts[0] - td[0], dt1 = ts[1] - td[1], dt2 = ts[2] - td[2];
        t0 = Rd[0][0]*dt0 + Rd[1][0]*dt1 + Rd[2][0]*dt2;
        t1 = Rd[0][1]*dt0 + Rd[1][1]*dt1 + Rd[2][1]*dt2;
        t2 = Rd[0][2]*dt0 + Rd[1][2]*dt1 + Rd[2][2]*dt2;
        dec3(w + 161, t0, t1, t2);

        // pos embedding (cols 180..195): f32 Cody-Waite + fast sin/cos
        float dd = (float)(s - d);
#pragma unroll
        for (int j = 0; j < 8; j++) {
            float ang = __fmul_rn(dd, c_posfreq[j]);
            float si, co;
            fast_sincos(ang, &si, &co);
            w[180 + j] = co;
            w[188 + j] = si;
        }

        // E_bias (cols 196..212): decouple of a 1-vector -> 1 direct + 16 RBF
        float bb = (float)(node_idx[s] - node_idx[d]);
        float nb = sqrtf(bb * bb + 1e-12f);
        float ib = (nb < 1e-4f) ? 0.f : __fdividef(1.f, nb + 1e-6f);
        w[196] = bb * ib;
        float ab = 0.8f * nb;
#pragma unroll
        for (int r = 0; r < 16; r++) {
            float u = ab - (float)r * 1.0666666666666667f;
            w[197 + r] = __expf(-u * u);
        }

        // edge index outputs (coalesced scalar)
        stg(out, OFF_EIDX + e,      (float)eix[e],     LIM);
        stg(out, OFF_EIDX + ET + e, (float)eix[E + e], LIM);
    }
    __syncthreads();

    // big contiguous coalesced float4 copy out (smem layout == global layout)
    int rem   = min(TILE, E - e0);
    {
        int total = rem * EW;
        long long base = OFF_E + (long long)e0 * EW;   // mult of 4
        float4* g4 = reinterpret_cast<float4*>(out + base);
        const float4* s4 = reinterpret_cast<const float4*>(sm);
        int n4 = total >> 2;
        long long lim4 = (LIM - base) >> 2;
        for (int k4 = tid; k4 < n4; k4 += TILE)
            if (k4 < lim4) g4[k4] = s4[k4];
        for (int k = (n4 << 2) + tid; k < total; k += TILE)
            stg(out, base + k, sm[k], LIM);
    }
    __syncthreads();

    // restage Tts_rot (Rts = Q^T) and Tts_trans in reused smem, coalesced out
    if (active) {
#pragma unroll
        for (int i = 0; i < 3; i++)
#pragma unroll
            for (int k = 0; k < 3; k++)
                sm[tid * 9 + 3 * i + k] = Q[k][i];
        sm[TILE * 9 + tid * 3 + 0] = t0;
        sm[TILE * 9 + tid * 3 + 1] = t1;
        sm[TILE * 9 + tid * 3 + 2] = t2;
    }
    __syncthreads();
    {
        int totR = rem * 9;
        long long baseR = OFF_TTSROT + (long long)e0 * 9;
        float4* g4 = reinterpret_cast<float4*>(out + baseR);
        const float4* s4 = reinterpret_cast<const float4*>(sm);
        int n4 = totR >> 2;
        long long lim4 = (LIM - baseR) >> 2;
        for (int k4 = tid; k4 < n4; k4 += TILE)
            if (k4 < lim4) g4[k4] = s4[k4];
        for (int k = (n4 << 2) + tid; k < totR; k += TILE)
            stg(out, baseR + k, sm[k], LIM);

        int totT = rem * 3;
        long long baseT = OFF_TTSTRANS + (long long)e0 * 3;
        for (int k = tid; k < totT; k += TILE)
            stg(out, baseT + k, sm[TILE * 9 + k], LIM);
    }
}

// ---------------------------------------------------------------------------
// Kernel 3: big zero fill for E_g (float4 contiguous)
// ---------------------------------------------------------------------------
__global__ void fill_zero4(float4* __restrict__ p, long long n4) {
    long long stride = (long long)gridDim.x * blockDim.x;
    for (long long i = blockIdx.x * (long long)blockDim.x + threadIdx.x; i < n4; i += stride)
        p[i] = make_float4(0.f, 0.f, 0.f, 0.f);
}

// ---------------------------------------------------------------------------
// Kernel 4: virtual-frame tails — 32-bit index arithmetic
// ---------------------------------------------------------------------------
__global__ void misc_kernel(const int* __restrict__ batch_id, float* __restrict__ out,
                            long long LIM, int N, int E,
                            long long OFF_V, long long OFF_TROT, long long OFF_TTRANS,
                            long long OFF_TTSROT, long long OFF_TTSTRANS,
                            long long OFF_BATCH, long long OFF_EIDX, long long OFF_CHAIN) {
    const unsigned KN = KF * (unsigned)N, G2 = 2u * KN, ET = (unsigned)E + G2, KB = KF * NB;
    const unsigned szA = G2 * 9u;
    const unsigned szB = G2 * 3u;
    const unsigned szC = 2u * G2;
    const unsigned szD = KB;
    const unsigned szE_ = KB;
    const unsigned szF = KB * 9u;
    const unsigned szG = KB * 3u;
    const unsigned szH = KB * 76u;
    const unsigned TOT = szA + szB + szC + szD + szE_ + szF + szG + szH;

    const unsigned bTTSROT  = (unsigned)OFF_TTSROT  + (unsigned)E * 9u;
    const unsigned bTTSTR   = (unsigned)OFF_TTSTRANS + (unsigned)E * 3u;
    const unsigned bEIDX    = (unsigned)OFF_EIDX;
    const unsigned bBATCH   = (unsigned)OFF_BATCH + (unsigned)N;
    const unsigned bCHAIN   = (unsigned)OFF_CHAIN + (unsigned)N;
    const unsigned bTROT    = (unsigned)OFF_TROT + (unsigned)N * 9u;
    const unsigned bTTRANS  = (unsigned)OFF_TTRANS + (unsigned)N * 3u;
    const unsigned bV       = (unsigned)OFF_V + (unsigned)N * 76u;
    const unsigned uN = (unsigned)N, uE = (unsigned)E;
    const unsigned uLIM = (unsigned)LIM;

    unsigned stride = gridDim.x * blockDim.x;
    for (unsigned i = blockIdx.x * blockDim.x + threadIdx.x; i < TOT; i += stride) {
        unsigned j = i;
        unsigned idx; float v;
        if (j < szA) {
            unsigned c = j % 9u;
            idx = bTTSROT + j; v = (c == 0u || c == 4u || c == 8u) ? 1.f : 0.f;
        } else if ((j -= szA) < szB) {
            idx = bTTSTR + j; v = 0.f;
        } else if ((j -= szB) < szC) {
            if (j < G2) {
                v = (j < KN) ? (float)(uN + (unsigned)batch_id[j % uN] + (j / uN) * NB)
                             : (float)((j - KN) % uN);
                idx = bEIDX + uE + j;
            } else {
                unsigned t = j - G2;
                v = (t < KN) ? (float)(t % uN)
                             : (float)(uN + (unsigned)batch_id[(t - KN) % uN] + ((t - KN) / uN) * NB);
                idx = bEIDX + ET + uE + t;
            }
        } else if ((j -= szC) < szD) {
            idx = bBATCH + j; v = (float)(j % NB);
        } else if ((j -= szD) < szE_) {
            idx = bCHAIN + j; v = 1001.f;
        } else if ((j -= szE_) < szF) {
            unsigned c = j % 9u;
            idx = bTROT + j; v = (c == 0u || c == 4u || c == 8u) ? 1.f : 0.f;
        } else if ((j -= szF) < szG) {
            idx = bTTRANS + j; v = 0.f;
        } else {
            j -= szG;
            unsigned r = j / 76u, c = j % 76u;
            unsigned k = r / NB;
            unsigned m = (c < 38u) ? c : c - 38u;
            double f = exp(-(double)(2u * m) * 9.210340371976184 / 76.0);
            double ang = (double)k * f;
            idx = bV + j; v = (float)((c < 38u) ? cos(ang) : sin(ang));
        }
        if (idx < uLIM) out[idx] = v;
    }
}

// ---------------------------------------------------------------------------
extern "C" void kernel_launch(void* const* d_in, const int* in_sizes, int n_in,
                              void* d_out, int out_size) {
    const float* X        = (const float*)d_in[0];
    const int*   node_idx = (const int*)d_in[1];
    const int*   eix      = (const int*)d_in[2];
    const int*   batch_id = (const int*)d_in[3];
    const int*   chain    = (const int*)d_in[4];
    float* out = (float*)d_out;

    int N = in_sizes[0] / 12;
    int E = in_sizes[2] / 2;
    int NT = N + KF * NB;
    int G2 = 2 * KF * N;
    int ET = E + G2;
    long long LIM = (long long)out_size;

    long long OFF_V        = 0;
    long long OFF_E        = OFF_V + (long long)NT * 76;
    long long OFF_TROT     = OFF_E + (long long)ET * EW;
    long long OFF_TTRANS   = OFF_TROT + (long long)NT * 9;
    long long OFF_TTSROT   = OFF_TTRANS + (long long)NT * 3;
    long long OFF_TTSTRANS = OFF_TTSROT + (long long)ET * 9;
    long long OFF_BATCH    = OFF_TTSTRANS + (long long)ET * 3;
    long long OFF_EIDX     = OFF_BATCH + NT;
    long long OFF_CHAIN    = OFF_EIDX + 2LL * ET;

    static bool attr_done = false;
    if (!attr_done) {
        cudaFuncSetAttribute(edge_kernel, cudaFuncAttributeMaxDynamicSharedMemorySize,
                             TILE * EW * (int)sizeof(float));
        attr_done = true;
    }

    node_kernel<<<(N + 127) / 128, 128>>>(X, batch_id, chain, out, LIM, N,
                                          OFF_V, OFF_TROT, OFF_TTRANS, OFF_BATCH, OFF_CHAIN);

    edge_kernel<<<(E + TILE - 1) / TILE, TILE, TILE * EW * sizeof(float)>>>(
        X, eix, node_idx, out, LIM, N, E, ET, OFF_E, OFF_TTSROT, OFF_TTSTRANS, OFF_EIDX);

    // E_g zero region: rows [E, ET) of E_out, contiguous & 16B-aligned
    long long zstart = OFF_E + (long long)E * EW;
    long long zcount = (long long)G2 * EW;
    long long n4 = zcount / 4;
    if (zstart + zcount <= LIM)
        fill_zero4<<<2048, 256>>>(reinterpret_cast<float4*>(out + zstart), n4);

    misc_kernel<<<2048, 256>>>(batch_id, out, LIM, N, E,
                               OFF_V, OFF_TROT, OFF_TTRANS, OFF_TTSROT, OFF_TTSTRANS,
                               OFF_BATCH, OFF_EIDX, OFF_CHAIN);
}

// round 4
// speedup vs baseline: 2.6868x; 1.1556x over previous
#include <cuda_runtime.h>
#include <math.h>

// GeoFeaturizer for GB300 (sm_103a). B=8 batches, K=3 virtual frames (fixed).
#define NB 8
#define KF 3
#define TILE 128       // edges per edge-block
#define EW 213         // edge feature width
#define NFB 888        // fill/misc blocks

// pos-embedding freqs: 10000^(-j/8) = 10^(-j/2)
__constant__ float c_posfreq[8] = {
    1.0f, 0.31622776601683794f, 0.1f, 0.031622776601683794f,
    0.01f, 0.0031622776601683794f, 0.001f, 0.00031622776601683794f
};

__device__ __forceinline__ void stg(float* __restrict__ o, long long i, float v, long long lim) {
    if (i >= 0 && i < lim) o[i] = v;
}

// decouple() for a 3-vector: 3 direction comps + 16 RBF of the norm. All f32 fast-path.
__device__ __forceinline__ void dec3(float* __restrict__ w, float x, float y, float z) {
    float sq   = x*x + y*y + z*z;
    float norm = sqrtf(sq + 1e-12f);
    float inv  = (norm < 1e-4f) ? 0.f : __fdividef(1.f, norm + 1e-6f);
    w[0] = x * inv; w[1] = y * inv; w[2] = z * inv;
    float a = 0.8f * norm;
#pragma unroll
    for (int r = 0; r < 16; r++) {
        float u = a - (float)r * 1.0666666666666667f;
        w[3 + r] = __expf(-u * u);
    }
}

// f32 Cody-Waite reduction then fast sin/cos (|ang| <= ~3.2e4).
__device__ __forceinline__ void fast_sincos(float ang, float* s, float* c) {
    const float INV2PI = 0.15915494309189535f;
    const float PI2_HI = 6.28318548202514648f;
    const float PI2_LO = -1.74845553146357e-07f;
    float k = rintf(ang * INV2PI);
    float r = fmaf(-k, PI2_HI, ang);
    r = fmaf(-k, PI2_LO, r);
    *s = __sinf(r);
    *c = __cosf(r);
}

// Frame from atoms 0,1,2 (N, CA, C). R is the reference's stored R (= M^T).
__device__ __forceinline__ void make_frame(const float a0[3], const float a1[3], const float a2[3],
                                           float R[3][3]) {
    float nx = a0[0] - a1[0], ny_ = a0[1] - a1[1], nz_ = a0[2] - a1[2];
    float cx = a2[0] - a1[0], cy  = a2[1] - a1[1], cz  = a2[2] - a1[2];
    const float EPSf = 1e-20f;
    float nrm  = sqrtf(EPSf + cx*cx + cy*cy);
    float s1 = -cy / nrm, c1 = cx / nrm;
    float nrm2 = sqrtf(EPSf + cx*cx + cy*cy + cz*cz);
    float s2 = cz / nrm2;
    float c2 = sqrtf(cx*cx + cy*cy) / nrm2;
    float Rc[3][3] = {
        { c2*c1, -c2*s1, s2 },
        { s1,     c1,    0.f},
        {-s2*c1,  s2*s1, c2 }
    };
    float nr1 = Rc[1][0]*nx + Rc[1][1]*ny_;
    float nr2 = Rc[2][0]*nx + Rc[2][1]*ny_ + Rc[2][2]*nz_;
    float nrm3 = sqrtf(EPSf + nr1*nr1 + nr2*nr2);
    float sn = -nr2 / nrm3, cn = nr1 / nrm3;
    float M1[3], M2[3];
#pragma unroll
    for (int j = 0; j < 3; j++) {
        M1[j] = cn * Rc[1][j] - sn * Rc[2][j];
        M2[j] = sn * Rc[1][j] + cn * Rc[2][j];
    }
    // R = M^T: columns of M become rows of R
#pragma unroll
    for (int j = 0; j < 3; j++) {
        R[j][0] = Rc[0][j];
        R[j][1] = M1[j];
        R[j][2] = M2[j];
    }
}

// ---------------------------------------------------------------------------
// One fused kernel, three block roles: [0,nEB) edges, [nEB,nEB+nNB) nodes,
// rest: zero-fill + misc tails. All roles independent (frames computed inline).
// ---------------------------------------------------------------------------
__global__ void __launch_bounds__(128, 2)
fused_kernel(const float* __restrict__ X,
             const int*  __restrict__ node_idx,
             const int*  __restrict__ eix,       // (2, E) row-major
             const int*  __restrict__ batch_id,
             const int*  __restrict__ chain,
             float* __restrict__ out, long long LIM,
             int N, int E, int nEB, int nNB,
             long long OFF_V, long long OFF_E, long long OFF_TROT,
             long long OFF_TTRANS, long long OFF_TTSROT, long long OFF_TTSTRANS,
             long long OFF_BATCH, long long OFF_EIDX, long long OFF_CHAIN) {
    extern __shared__ float sm[];
    int tid = threadIdx.x;
    int bid = blockIdx.x;
    const int ET = E + 2 * KF * N;

    if (bid < nEB) {
        // ------------------------------------------------ edge role
        int e0 = bid * TILE;
        int e  = e0 + tid;
        bool active = (e < E);

        float Q[3][3];
        float t0 = 0.f, t1 = 0.f, t2 = 0.f;

        if (active) {
            float* w = sm + tid * EW;
            int s = min(max(eix[e], 0), N - 1);
            int d = min(max(eix[E + e], 0), N - 1);

            const float4* Xs4 = reinterpret_cast<const float4*>(X) + (size_t)s * 3;
            const float4* Xd4 = reinterpret_cast<const float4*>(X) + (size_t)d * 3;
            float4 sa = Xs4[0], sb = Xs4[1], sc = Xs4[2];
            float4 da = Xd4[0], db = Xd4[1], dc = Xd4[2];
            float P[8][3] = {
                {sa.x, sa.y, sa.z}, {sa.w, sb.x, sb.y}, {sb.z, sb.w, sc.x}, {sc.y, sc.z, sc.w},
                {da.x, da.y, da.z}, {da.w, db.x, db.y}, {db.z, db.w, dc.x}, {dc.y, dc.z, dc.w}
            };

            float Rs[3][3], Rd[3][3];
            make_frame(P[0], P[1], P[2], Rs);
            make_frame(P[4], P[5], P[6], Rd);
            float ts[3] = {P[1][0], P[1][1], P[1][2]};
            float td[3] = {P[5][0], P[5][1], P[5][2]};

            // diffE: loc = Rs^T (p - t_src), decoupled (cols 0..151)
#pragma unroll
            for (int a8 = 0; a8 < 8; a8++) {
                float q0 = P[a8][0] - ts[0], q1 = P[a8][1] - ts[1], q2 = P[a8][2] - ts[2];
                float l0 = Rs[0][0]*q0 + Rs[1][0]*q1 + Rs[2][0]*q2;
                float l1 = Rs[0][1]*q0 + Rs[1][1]*q1 + Rs[2][1]*q2;
                float l2 = Rs[0][2]*q0 + Rs[1][2]*q1 + Rs[2][2]*q2;
                dec3(w + a8 * 19, l0, l1, l2);
            }

            // Q = Rs^T Rd; E_quant (cols 152..160) = Q row-major
#pragma unroll
            for (int i = 0; i < 3; i++)
#pragma unroll
                for (int j = 0; j < 3; j++)
                    Q[i][j] = Rs[0][i]*Rd[0][j] + Rs[1][i]*Rd[1][j] + Rs[2][i]*Rd[2][j];
#pragma unroll
            for (int i = 0; i < 3; i++)
#pragma unroll
                for (int j = 0; j < 3; j++)
                    w[152 + 3 * i + j] = Q[i][j];

            // tts = Rd^T (t_src - t_dst); E_trans (cols 161..179)
            float dt0 = ts[0] - td[0], dt1 = ts[1] - td[1], dt2 = ts[2] - td[2];
            t0 = Rd[0][0]*dt0 + Rd[1][0]*dt1 + Rd[2][0]*dt2;
            t1 = Rd[0][1]*dt0 + Rd[1][1]*dt1 + Rd[2][1]*dt2;
            t2 = Rd[0][2]*dt0 + Rd[1][2]*dt1 + Rd[2][2]*dt2;
            dec3(w + 161, t0, t1, t2);

            // pos embedding (cols 180..195)
            float dd = (float)(s - d);
#pragma unroll
            for (int j = 0; j < 8; j++) {
                float ang = __fmul_rn(dd, c_posfreq[j]);
                float si, co;
                fast_sincos(ang, &si, &co);
                w[180 + j] = co;
                w[188 + j] = si;
            }

            // E_bias (cols 196..212)
            float bb = (float)(node_idx[s] - node_idx[d]);
            float nb = sqrtf(bb * bb + 1e-12f);
            float ib = (nb < 1e-4f) ? 0.f : __fdividef(1.f, nb + 1e-6f);
            w[196] = bb * ib;
            float ab = 0.8f * nb;
#pragma unroll
            for (int r = 0; r < 16; r++) {
                float u = ab - (float)r * 1.0666666666666667f;
                w[197 + r] = __expf(-u * u);
            }

            stg(out, OFF_EIDX + e,      (float)eix[e],     LIM);
            stg(out, OFF_EIDX + ET + e, (float)eix[E + e], LIM);
        }
        __syncthreads();

        int rem = min(TILE, E - e0);
        {
            int total = rem * EW;
            long long base = OFF_E + (long long)e0 * EW;
            float4* g4 = reinterpret_cast<float4*>(out + base);
            const float4* s4 = reinterpret_cast<const float4*>(sm);
            int n4 = total >> 2;
            long long lim4 = (LIM - base) >> 2;
            for (int k4 = tid; k4 < n4; k4 += TILE)
                if (k4 < lim4) g4[k4] = s4[k4];
            for (int k = (n4 << 2) + tid; k < total; k += TILE)
                stg(out, base + k, sm[k], LIM);
        }
        __syncthreads();

        // restage Tts_rot (Rts = Q^T) and Tts_trans, coalesced out
        if (active) {
#pragma unroll
            for (int i = 0; i < 3; i++)
#pragma unroll
                for (int k = 0; k < 3; k++)
                    sm[tid * 9 + 3 * i + k] = Q[k][i];
            sm[TILE * 9 + tid * 3 + 0] = t0;
            sm[TILE * 9 + tid * 3 + 1] = t1;
            sm[TILE * 9 + tid * 3 + 2] = t2;
        }
        __syncthreads();
        {
            int totR = rem * 9;
            long long baseR = OFF_TTSROT + (long long)e0 * 9;
            float4* g4 = reinterpret_cast<float4*>(out + baseR);
            const float4* s4 = reinterpret_cast<const float4*>(sm);
            int n4 = totR >> 2;
            long long lim4 = (LIM - baseR) >> 2;
            for (int k4 = tid; k4 < n4; k4 += TILE)
                if (k4 < lim4) g4[k4] = s4[k4];
            for (int k = (n4 << 2) + tid; k < totR; k += TILE)
                stg(out, baseR + k, sm[k], LIM);

            int totT = rem * 3;
            long long baseT = OFF_TTSTRANS + (long long)e0 * 3;
            for (int k = tid; k < totT; k += TILE)
                stg(out, baseT + k, sm[TILE * 9 + k], LIM);
        }
    } else if (bid < nEB + nNB) {
        // ------------------------------------------------ node role
        int n0 = (bid - nEB) * 128;
        int n  = n0 + tid;
        float* sv = sm;   // 128*76 floats

        if (n < N) {
            const float4* X4 = reinterpret_cast<const float4*>(X) + (size_t)n * 3;
            float4 xa = X4[0], xb = X4[1], xc = X4[2];
            float ax[4][3] = {
                {xa.x, xa.y, xa.z}, {xa.w, xb.x, xb.y},
                {xb.z, xb.w, xc.x}, {xc.y, xc.z, xc.w}
            };
            float R[3][3];
            make_frame(ax[0], ax[1], ax[2], R);

#pragma unroll
            for (int i = 0; i < 3; i++)
#pragma unroll
                for (int j = 0; j < 3; j++)
                    stg(out, OFF_TROT + (long long)n * 9 + 3 * i + j, R[i][j], LIM);
            stg(out, OFF_TTRANS + (long long)n * 3 + 0, ax[1][0], LIM);
            stg(out, OFF_TTRANS + (long long)n * 3 + 1, ax[1][1], LIM);
            stg(out, OFF_TTRANS + (long long)n * 3 + 2, ax[1][2], LIM);
            stg(out, OFF_BATCH + n, (float)batch_id[n], LIM);
            stg(out, OFF_CHAIN + n, (float)chain[n], LIM);

            bool start = (n == 0) || (batch_id[n] != batch_id[n - 1]);
            float prev0 = 0.f, prev1 = 0.f, prev2 = 0.f;
            if (n > 0) {
                const float* xp = X + (size_t)(n - 1) * 12 + 9;
                prev0 = xp[0]; prev1 = xp[1]; prev2 = xp[2];
            }
            float* wv = sv + tid * 76;
#pragma unroll
            for (int a = 0; a < 4; a++) {
                float dx, dy, dz;
                if (start) { dx = dy = dz = 0.f; }
                else {
                    float px, py, pz;
                    if (a == 0) { px = prev0; py = prev1; pz = prev2; }
                    else        { px = ax[a-1][0]; py = ax[a-1][1]; pz = ax[a-1][2]; }
                    dx = ax[a][0] - px; dy = ax[a][1] - py; dz = ax[a][2] - pz;
                }
                float l0 = R[0][0]*dx + R[1][0]*dy + R[2][0]*dz;
                float l1 = R[0][1]*dx + R[1][1]*dy + R[2][1]*dz;
                float l2 = R[0][2]*dx + R[1][2]*dy + R[2][2]*dz;
                dec3(wv + a * 19, l0, l1, l2);
            }
        }
        __syncthreads();

        int rem = min(128, N - n0);
        if (rem > 0) {
            int total = rem * 76;
            long long base = OFF_V + (long long)n0 * 76;
            float4* g4 = reinterpret_cast<float4*>(out + base);
            const float4* s4 = reinterpret_cast<const float4*>(sv);
            int n4 = total >> 2;
            long long lim4 = (LIM - base) >> 2;
            for (int k4 = tid; k4 < n4; k4 += 128)
                if (k4 < lim4) g4[k4] = s4[k4];
        }
    } else {
        // ------------------------------------------------ fill + misc role
        const unsigned KN = KF * (unsigned)N, G2 = 2u * KN, uET = (unsigned)E + G2, KB = KF * NB;
        const unsigned zelems = G2 * (unsigned)EW;          // E_g zeros (float count)
        const unsigned zn4 = zelems >> 2;                   // divisible by 4
        const unsigned szA = G2 * 9u;
        const unsigned szB = G2 * 3u;
        const unsigned szC = 2u * G2;
        const unsigned szD = KB;
        const unsigned szE_ = KB;
        const unsigned szF = KB * 9u;
        const unsigned szG = KB * 3u;
        const unsigned szH = KB * 76u;
        const unsigned TOT = zn4 + szA + szB + szC + szD + szE_ + szF + szG + szH;

        const unsigned zbase4 = (unsigned)((OFF_E + (long long)E * EW) >> 2);
        const unsigned bTTSROT = (unsigned)OFF_TTSROT + (unsigned)E * 9u;
        const unsigned bTTSTR  = (unsigned)OFF_TTSTRANS + (unsigned)E * 3u;
        const unsigned bEIDX   = (unsigned)OFF_EIDX;
        const unsigned bBATCH  = (unsigned)OFF_BATCH + (unsigned)N;
        const unsigned bCHAIN  = (unsigned)OFF_CHAIN + (unsigned)N;
        const unsigned bTROT   = (unsigned)OFF_TROT + (unsigned)N * 9u;
        const unsigned bTTRANS = (unsigned)OFF_TTRANS + (unsigned)N * 3u;
        const unsigned bV      = (unsigned)OFF_V + (unsigned)N * 76u;
        const unsigned uN = (unsigned)N, uE = (unsigned)E;
        const unsigned uLIM = (unsigned)LIM;
        float4* out4 = reinterpret_cast<float4*>(out);

        unsigned fb = (unsigned)(bid - nEB - nNB);
        unsigned stride = (unsigned)NFB * 128u;
        for (unsigned i = fb * 128u + tid; i < TOT; i += stride) {
            if (i < zn4) {
                unsigned i4 = zbase4 + i;
                if (((long long)i4 << 2) + 3 < LIM)
                    out4[i4] = make_float4(0.f, 0.f, 0.f, 0.f);
                continue;
            }
            unsigned j = i - zn4;
            unsigned idx; float v;
            if (j < szA) {
                unsigned c = j % 9u;
                idx = bTTSROT + j; v = (c == 0u || c == 4u || c == 8u) ? 1.f : 0.f;
            } else if ((j -= szA) < szB) {
                idx = bTTSTR + j; v = 0.f;
            } else if ((j -= szB) < szC) {
                if (j < G2) {
                    v = (j < KN) ? (float)(uN + (unsigned)batch_id[j % uN] + (j / uN) * NB)
                                 : (float)((j - KN) % uN);
                    idx = bEIDX + uE + j;
                } else {
                    unsigned t = j - G2;
                    v = (t < KN) ? (float)(t % uN)
                                 : (float)(uN + (unsigned)batch_id[(t - KN) % uN] + ((t - KN) / uN) * NB);
                    idx = bEIDX + uET + uE + t;
                }
            } else if ((j -= szC) < szD) {
                idx = bBATCH + j; v = (float)(j % NB);
            } else if ((j -= szD) < szE_) {
                idx = bCHAIN + j; v = 1001.f;
            } else if ((j -= szE_) < szF) {
                unsigned c = j % 9u;
                idx = bTROT + j; v = (c == 0u || c == 4u || c == 8u) ? 1.f : 0.f;
            } else if ((j -= szF) < szG) {
                idx = bTTRANS + j; v = 0.f;
            } else {
                j -= szG;
                unsigned r = j / 76u, c = j % 76u;
                unsigned k = r / NB;
                unsigned m = (c < 38u) ? c : c - 38u;
                double f = exp(-(double)(2u * m) * 9.210340371976184 / 76.0);
                double ang = (double)k * f;
                idx = bV + j; v = (float)((c < 38u) ? cos(ang) : sin(ang));
            }
            if (idx < uLIM) out[idx] = v;
        }
    }
}

// ---------------------------------------------------------------------------
extern "C" void kernel_launch(void* const* d_in, const int* in_sizes, int n_in,
                              void* d_out, int out_size) {
    const float* X        = (const float*)d_in[0];
    const int*   node_idx = (const int*)d_in[1];
    const int*   eix      = (const int*)d_in[2];
    const int*   batch_id = (const int*)d_in[3];
    const int*   chain    = (const int*)d_in[4];
    float* out = (float*)d_out;

    int N = in_sizes[0] / 12;
    int E = in_sizes[2] / 2;
    int NT = N + KF * NB;
    int G2 = 2 * KF * N;
    int ET = E + G2;
    long long LIM = (long long)out_size;

    long long OFF_V        = 0;
    long long OFF_E        = OFF_V + (long long)NT * 76;
    long long OFF_TROT     = OFF_E + (long long)ET * EW;
    long long OFF_TTRANS   = OFF_TROT + (long long)NT * 9;
    long long OFF_TTSROT   = OFF_TTRANS + (long long)NT * 3;
    long long OFF_TTSTRANS = OFF_TTSROT + (long long)ET * 9;
    long long OFF_BATCH    = OFF_TTSTRANS + (long long)ET * 3;
    long long OFF_EIDX     = OFF_BATCH + NT;
    long long OFF_CHAIN    = OFF_EIDX + 2LL * ET;

    int nEB = (E + TILE - 1) / TILE;
    int nNB = (N + 127) / 128;
    int grid = nEB + nNB + NFB;
    int smem = TILE * EW * (int)sizeof(float);

    static bool attr_done = false;
    if (!attr_done) {
        cudaFuncSetAttribute(fused_kernel, cudaFuncAttributeMaxDynamicSharedMemorySize, smem);
        attr_done = true;
    }

    fused_kernel<<<grid, 128, smem>>>(X, node_idx, eix, batch_id, chain, out, LIM,
                                      N, E, nEB, nNB,
                                      OFF_V, OFF_E, OFF_TROT, OFF_TTRANS,
                                      OFF_TTSROT, OFF_TTSTRANS,
                                      OFF_BATCH, OFF_EIDX, OFF_CHAIN);
}